// round 7
// baseline (speedup 1.0000x reference)
#include <cuda_runtime.h>
#include <cuda_fp16.h>
#include <cstdint>

// Problem constants (dataset-fixed shapes).
static constexpr int NN    = 50000;      // nodes
static constexpr int HIDC  = 64;         // hidden/z dim
static constexpr int INDIM = 128;
static constexpr int N64   = NN * HIDC;  // 3,200,000
static constexpr int ECAP  = 1000000;    // edge capacity (dataset: 800000)
static constexpr int SCAN_BLK = 512;
static constexpr int SCAN_NB  = (NN + SCAN_BLK - 1) / SCAN_BLK;  // 98

static constexpr unsigned long long FLAG_AGG = 1ull << 40;
static constexpr unsigned long long FLAG_INC = 2ull << 40;
static constexpr unsigned long long VAL_MASK = (1ull << 40) - 1;

// ---- scratch (device globals; no allocations allowed) ----
__device__ int    g_cnt[NN];
__device__ int    g_offs[NN + 1];
__device__ int    g_cursor[NN];
__device__ unsigned long long g_scanstate[SCAN_NB];
__device__ int2   g_edge[ECAP];       // (src, bitcast(norm)) sorted by dst bucket
__device__ float  g_dinv[NN];
__device__ __half g_XW[N64];          // x @ W1  (fp16 storage, fp32 math)
__device__ __half g_h1[N64];          // ELU(conv1)
__device__ float  g_sums[2 * 64 * 64];
__device__ float  g_cntf[64];

// ---------------- helpers ----------------
__device__ __forceinline__ void red_add_f32x4(float* p, float4 v) {
    asm volatile("red.global.add.v4.f32 [%0], {%1,%2,%3,%4};"
                 :: "l"(p), "f"(v.x), "f"(v.y), "f"(v.z), "f"(v.w) : "memory");
}
__device__ __forceinline__ void red_add_f32(float* p, float v) {
    asm volatile("red.global.add.f32 [%0], %1;" :: "l"(p), "f"(v) : "memory");
}
__device__ __forceinline__ float elu1(float x) { return x > 0.0f ? x : expm1f(x); }
__device__ __forceinline__ float4 elu4(float4 v) {
    v.x = elu1(v.x); v.y = elu1(v.y); v.z = elu1(v.z); v.w = elu1(v.w);
    return v;
}
__device__ __forceinline__ float4 fma4(float4 a, float s, float4 acc) {
    acc.x += a.x * s; acc.y += a.y * s; acc.z += a.z * s; acc.w += a.w * s;
    return acc;
}
__device__ __forceinline__ float4 add4(float4 a, float4 b) {
    a.x += b.x; a.y += b.y; a.z += b.z; a.w += b.w; return a;
}
// accumulate 8 halves (one uint4) scaled by w into acc[8]
__device__ __forceinline__ void fma8h(float* acc, uint4 raw, float w) {
    const __half2* h = reinterpret_cast<const __half2*>(&raw);
#pragma unroll
    for (int j = 0; j < 4; j++) {
        float2 f = __half22float2(h[j]);
        acc[2 * j]     += f.x * w;
        acc[2 * j + 1] += f.y * w;
    }
}
__device__ __forceinline__ uint4 pack8h(const float* a) {
    uint4 out;
    __half2* h = reinterpret_cast<__half2*>(&out);
#pragma unroll
    for (int j = 0; j < 4; j++) h[j] = __floats2half2_rn(a[2 * j], a[2 * j + 1]);
    return out;
}

// Warp-per-node CSR gather: lane = e_sub(0..3)*8 + c(0..7); each step handles
// 8 edges (two groups of 4) with leader-load + shfl broadcast of edge records.
// On return acc[8] holds the full neighbor sum for slice c (all lanes hold it).
__device__ __forceinline__ void warp_gather(const __half* __restrict__ F,
                                            int node, int lane, float* acc) {
    const int e_sub = lane >> 3;
    const int c     = lane & 7;
    const int ldlane = e_sub << 3;     // leader lane of this group
    float acc2[8];
#pragma unroll
    for (int j = 0; j < 8; j++) { acc[j] = 0.f; acc2[j] = 0.f; }

    int beg = g_offs[node], end = g_offs[node + 1];
    for (int k = beg; k < end; k += 8) {
        int e0 = k + e_sub;
        int e1 = k + 4 + e_sub;
        int2 p0 = make_int2(0, 0), p1 = make_int2(0, 0);
        if (c == 0) {
            if (e0 < end) p0 = g_edge[e0];
            if (e1 < end) p1 = g_edge[e1];
        }
        int   s0 = __shfl_sync(0xFFFFFFFFu, p0.x, ldlane);
        float w0 = __int_as_float(__shfl_sync(0xFFFFFFFFu, p0.y, ldlane));
        int   s1 = __shfl_sync(0xFFFFFFFFu, p1.x, ldlane);
        float w1 = __int_as_float(__shfl_sync(0xFFFFFFFFu, p1.y, ldlane));
        if (e0 < end) {
            uint4 v = *reinterpret_cast<const uint4*>(&F[(long long)s0 * HIDC + c * 8]);
            fma8h(acc, v, w0);
        }
        if (e1 < end) {
            uint4 v = *reinterpret_cast<const uint4*>(&F[(long long)s1 * HIDC + c * 8]);
            fma8h(acc2, v, w1);
        }
    }
    // combine the 4 edge-groups (lanes differing in bits 3,4 share the same c)
#pragma unroll
    for (int j = 0; j < 8; j++) {
        float v = acc[j] + acc2[j];
        v += __shfl_xor_sync(0xFFFFFFFFu, v, 8);
        v += __shfl_xor_sync(0xFFFFFFFFu, v, 16);
        acc[j] = v;
    }
}

// ---------------- kernels ----------------

__global__ void k_zero() {
    int i = blockIdx.x * blockDim.x + threadIdx.x;
    if (i < NN) g_cnt[i] = 0;
    if (i < SCAN_NB) g_scanstate[i] = 0ull;
    if (i < 2 * 64 * 64) g_sums[i] = 0.f;
    if (i < 64) g_cntf[i] = 0.f;
}

__global__ void k_deg(const int* __restrict__ dst, int E) {
    int e = blockIdx.x * blockDim.x + threadIdx.x;
    if (e < E) atomicAdd(&g_cnt[dst[e]], 1);
}

// Single-pass scan with warp-parallel decoupled lookback.
// Also computes dinv and initializes cursors.
__global__ __launch_bounds__(SCAN_BLK) void k_scan(int N, int E) {
    __shared__ int wsum[16];
    __shared__ int sh_excl;
    const int tid  = threadIdx.x;
    const int lane = tid & 31;
    const int w    = tid >> 5;
    const int b    = blockIdx.x;
    const int i    = b * SCAN_BLK + tid;

    int v = (i < N) ? g_cnt[i] : 0;
    if (i < N) g_dinv[i] = rsqrtf((float)v + 1.0f);  // +1 self loop

    // in-warp inclusive scan
    int inc = v;
#pragma unroll
    for (int off = 1; off < 32; off <<= 1) {
        int t = __shfl_up_sync(0xFFFFFFFFu, inc, off);
        if (lane >= off) inc += t;
    }
    if (lane == 31) wsum[w] = inc;
    __syncthreads();

    if (w == 0) {
        int wv = (lane < 16) ? wsum[lane] : 0;
        int winc = wv;
#pragma unroll
        for (int off = 1; off < 16; off <<= 1) {
            int t = __shfl_up_sync(0xFFFFFFFFu, winc, off);
            if (lane >= off) winc += t;
        }
        if (lane < 16) wsum[lane] = winc - wv;   // exclusive warp base
        int btot = __shfl_sync(0xFFFFFFFFu, winc, 15);

        if (lane == 0 && b > 0)
            atomicExch(&g_scanstate[b], FLAG_AGG | (unsigned long long)btot);

        int excl = 0;
        if (b > 0) {
            int j = b - 1;
            while (true) {
                int idx = j - lane;
                unsigned long long s = 0;
                if (idx >= 0) {
                    do { s = atomicAdd(&g_scanstate[idx], 0ull); } while (s < FLAG_AGG);
                }
                unsigned incmask = __ballot_sync(0xFFFFFFFFu, idx >= 0 && s >= FLAG_INC);
                if (incmask) {
                    int first = __ffs(incmask) - 1;
                    int val = (lane <= first) ? (int)(s & VAL_MASK) : 0;
#pragma unroll
                    for (int off = 16; off; off >>= 1) val += __shfl_xor_sync(0xFFFFFFFFu, val, off);
                    excl += val;
                    break;
                } else {
                    int val = (idx >= 0) ? (int)(s & VAL_MASK) : 0;
#pragma unroll
                    for (int off = 16; off; off >>= 1) val += __shfl_xor_sync(0xFFFFFFFFu, val, off);
                    excl += val;
                    j -= 32;
                    if (j < 0) break;  // safety (block 0 always publishes INC)
                }
            }
        }
        if (lane == 0) {
            atomicExch(&g_scanstate[b], FLAG_INC | (unsigned long long)(excl + btot));
            sh_excl = excl;
        }
    }
    __syncthreads();

    int my_excl = sh_excl + wsum[w] + inc - v;
    if (i < N) { g_offs[i] = my_excl; g_cursor[i] = my_excl; }
    if (b == 0 && tid == 0) g_offs[N] = E;
}

__global__ void k_fill(const int* __restrict__ src, const int* __restrict__ dst, int E) {
    int e = blockIdx.x * blockDim.x + threadIdx.x;
    if (e < E) {
        int d = dst[e];
        int s = src[e];
        int pos = atomicAdd(&g_cursor[d], 1);
        g_edge[pos] = make_int2(s, __float_as_int(g_dinv[s] * g_dinv[d]));
    }
}

// GEMM1: X[N,128] @ W[128,64] -> g_XW (fp16). 128 rows/block, 256 threads, 8 rows/thread.
__global__ __launch_bounds__(256) void k_gemm1(const float* __restrict__ X,
                                               const float* __restrict__ W, int N) {
    __shared__ float Ws[INDIM * HIDC];
    for (int i = threadIdx.x; i < INDIM * HIDC / 4; i += 256)
        reinterpret_cast<float4*>(Ws)[i] = reinterpret_cast<const float4*>(W)[i];
    __syncthreads();

    const int q  = threadIdx.x & 15;
    const int rg = threadIdx.x >> 4;       // 0..15
    const int row0 = blockIdx.x * 128;

    float4 acc[8];
    int rows[8]; bool valid[8];
#pragma unroll
    for (int rr = 0; rr < 8; rr++) {
        rows[rr] = row0 + rg + 16 * rr;
        valid[rr] = rows[rr] < N;
        acc[rr] = make_float4(0.f, 0.f, 0.f, 0.f);
    }

    for (int k4 = 0; k4 < INDIM / 4; k4++) {
        float4 a[8];
#pragma unroll
        for (int rr = 0; rr < 8; rr++)
            a[rr] = valid[rr]
                ? reinterpret_cast<const float4*>(&X[(long long)rows[rr] * INDIM + k4 * 4])[0]
                : make_float4(0.f, 0.f, 0.f, 0.f);
#pragma unroll
        for (int kk = 0; kk < 4; kk++) {
            float4 w = reinterpret_cast<const float4*>(&Ws[(k4 * 4 + kk) * HIDC + q * 4])[0];
#pragma unroll
            for (int rr = 0; rr < 8; rr++) {
                float av = (&a[rr].x)[kk];
                acc[rr] = fma4(w, av, acc[rr]);
            }
        }
    }
#pragma unroll
    for (int rr = 0; rr < 8; rr++) {
        if (valid[rr]) {
            uint2 p;
            reinterpret_cast<__half2*>(&p)[0] = __floats2half2_rn(acc[rr].x, acc[rr].y);
            reinterpret_cast<__half2*>(&p)[1] = __floats2half2_rn(acc[rr].z, acc[rr].w);
            *reinterpret_cast<uint2*>(&g_XW[(long long)rows[rr] * HIDC + q * 4]) = p;
        }
    }
}

// Layer-1 gather (warp per node) + self-loop + bias + ELU -> g_h1.
__global__ void k_gather1(const float* __restrict__ b1, int N) {
    int gw = (int)((blockIdx.x * (long long)blockDim.x + threadIdx.x) >> 5);
    if (gw >= N) return;
    const int lane = threadIdx.x & 31;
    const int node = gw;
    const int c    = lane & 7;
    const int e_sub = lane >> 3;

    float acc[8];
    warp_gather(g_XW, node, lane, acc);

    if (e_sub == 0) {
        float di = g_dinv[node];
        float self = di * di;
        uint4 sv = *reinterpret_cast<const uint4*>(&g_XW[(long long)node * HIDC + c * 8]);
        const __half2* h = reinterpret_cast<const __half2*>(&sv);
        float4 bb0 = reinterpret_cast<const float4*>(&b1[c * 8])[0];
        float4 bb1 = reinterpret_cast<const float4*>(&b1[c * 8 + 4])[0];
        const float* bb = &bb0.x;  // bb0,bb1 contiguous on stack? use explicit
#pragma unroll
        for (int j = 0; j < 4; j++) {
            float2 f = __half22float2(h[j]);
            acc[2 * j]     += f.x * self;
            acc[2 * j + 1] += f.y * self;
        }
        acc[0] += bb0.x; acc[1] += bb0.y; acc[2] += bb0.z; acc[3] += bb0.w;
        acc[4] += bb1.x; acc[5] += bb1.y; acc[6] += bb1.z; acc[7] += bb1.w;
        (void)bb;
#pragma unroll
        for (int j = 0; j < 8; j++) acc[j] = elu1(acc[j]);
        *reinterpret_cast<uint4*>(&g_h1[(long long)node * HIDC + c * 8]) = pack8h(acc);
    }
}

// Fused layer-2: warp-per-node gather of h1 into smem tile (64 nodes), then
// z = tile @ {Wmu,Wsig} + bias, ELU, mean-pool accumulate. 256 threads/block.
__global__ __launch_bounds__(256) void k_gather2gemm2pool(
        const float* __restrict__ Wmu, const float* __restrict__ bmu,
        const float* __restrict__ Wsig, const float* __restrict__ bsig,
        const int* __restrict__ batch, int N) {
    __shared__ float Wms[HIDC * HIDC];
    __shared__ float Wss[HIDC * HIDC];
    __shared__ float tile[64 * HIDC];   // 16 KB
    __shared__ float spool[128];        // 64 mu + 64 sig

    for (int i = threadIdx.x; i < HIDC * HIDC / 4; i += 256) {
        reinterpret_cast<float4*>(Wms)[i] = reinterpret_cast<const float4*>(Wmu)[i];
        reinterpret_cast<float4*>(Wss)[i] = reinterpret_cast<const float4*>(Wsig)[i];
    }
    if (threadIdx.x < 128) spool[threadIdx.x] = 0.f;

    const int row0 = blockIdx.x * 64;
    const int wid  = threadIdx.x >> 5;    // 0..7
    const int lane = threadIdx.x & 31;
    const int c    = lane & 7;
    const int e_sub = lane >> 3;

    // ---- Phase A: warp per node, 8 nodes per warp ----
#pragma unroll
    for (int p = 0; p < 8; p++) {
        int ln = wid * 8 + p;
        int node = row0 + ln;
        float acc[8];
        if (node < N) {
            warp_gather(g_h1, node, lane, acc);
            if (e_sub == 0) {
                float di = g_dinv[node];
                float self = di * di;
                uint4 sv = *reinterpret_cast<const uint4*>(&g_h1[(long long)node * HIDC + c * 8]);
                const __half2* h = reinterpret_cast<const __half2*>(&sv);
#pragma unroll
                for (int j = 0; j < 4; j++) {
                    float2 f = __half22float2(h[j]);
                    acc[2 * j]     += f.x * self;
                    acc[2 * j + 1] += f.y * self;
                }
            }
        } else {
#pragma unroll
            for (int j = 0; j < 8; j++) acc[j] = 0.f;
        }
        if (e_sub == 0) {
            reinterpret_cast<float4*>(&tile[ln * HIDC + c * 8])[0] =
                make_float4(acc[0], acc[1], acc[2], acc[3]);
            reinterpret_cast<float4*>(&tile[ln * HIDC + c * 8 + 4])[0] =
                make_float4(acc[4], acc[5], acc[6], acc[7]);
        }
    }
    __syncthreads();

    // ---- Phase B: dual GEMM from smem + bias + ELU + pool ----
    const int q  = threadIdx.x & 15;
    const int rg = threadIdx.x >> 4;   // 0..15

    float4 am[4], as4[4];
    int rows[4]; bool valid[4];
#pragma unroll
    for (int rr = 0; rr < 4; rr++) {
        rows[rr] = row0 + rg + 16 * rr;
        valid[rr] = rows[rr] < N;
        am[rr]  = make_float4(0.f, 0.f, 0.f, 0.f);
        as4[rr] = make_float4(0.f, 0.f, 0.f, 0.f);
    }

    for (int k4 = 0; k4 < HIDC / 4; k4++) {
        float4 a[4];
#pragma unroll
        for (int rr = 0; rr < 4; rr++)
            a[rr] = reinterpret_cast<const float4*>(&tile[(rg + 16 * rr) * HIDC + k4 * 4])[0];
#pragma unroll
        for (int kk = 0; kk < 4; kk++) {
            float4 wm = reinterpret_cast<const float4*>(&Wms[(k4 * 4 + kk) * HIDC + q * 4])[0];
            float4 ws = reinterpret_cast<const float4*>(&Wss[(k4 * 4 + kk) * HIDC + q * 4])[0];
#pragma unroll
            for (int rr = 0; rr < 4; rr++) {
                float av = (&a[rr].x)[kk];
                am[rr]  = fma4(wm, av, am[rr]);
                as4[rr] = fma4(ws, av, as4[rr]);
            }
        }
    }

    float4 bbm = reinterpret_cast<const float4*>(&bmu[q * 4])[0];
    float4 bbs = reinterpret_cast<const float4*>(&bsig[q * 4])[0];
#pragma unroll
    for (int rr = 0; rr < 4; rr++) {
        am[rr]  = elu4(add4(am[rr], bbm));
        as4[rr] = elu4(add4(as4[rr], bbs));
    }

    int lastRow = min(row0 + 63, N - 1);
    int g0 = batch[row0];
    int g1 = batch[lastRow];

    if (g0 == g1) {
        float4 sm = make_float4(0.f, 0.f, 0.f, 0.f);
        float4 ss = make_float4(0.f, 0.f, 0.f, 0.f);
#pragma unroll
        for (int rr = 0; rr < 4; rr++) {
            if (valid[rr]) { sm = add4(sm, am[rr]); ss = add4(ss, as4[rr]); }
        }
        atomicAdd(&spool[q * 4 + 0], sm.x);
        atomicAdd(&spool[q * 4 + 1], sm.y);
        atomicAdd(&spool[q * 4 + 2], sm.z);
        atomicAdd(&spool[q * 4 + 3], sm.w);
        atomicAdd(&spool[64 + q * 4 + 0], ss.x);
        atomicAdd(&spool[64 + q * 4 + 1], ss.y);
        atomicAdd(&spool[64 + q * 4 + 2], ss.z);
        atomicAdd(&spool[64 + q * 4 + 3], ss.w);
        __syncthreads();
        if (threadIdx.x < 32) {
            int half = threadIdx.x >> 4;
            int cc   = threadIdx.x & 15;
            float4 v = reinterpret_cast<const float4*>(&spool[half * 64 + cc * 4])[0];
            red_add_f32x4(&g_sums[(long long)(half * 64 + g0) * HIDC + cc * 4], v);
        }
        if (threadIdx.x == 0) {
            int cnt = min(N - row0, 64);
            red_add_f32(&g_cntf[g0], (float)cnt);
        }
    } else {
#pragma unroll
        for (int rr = 0; rr < 4; rr++) {
            if (!valid[rr]) continue;
            int g = batch[rows[rr]];
            red_add_f32x4(&g_sums[(long long)(0 * 64 + g) * HIDC + q * 4], am[rr]);
            red_add_f32x4(&g_sums[(long long)(1 * 64 + g) * HIDC + q * 4], as4[rr]);
            if (q == 0) red_add_f32(&g_cntf[g], 1.0f);
        }
    }
}

// Final: divide by counts, write [z_mu ; z_sigma] to d_out.
__global__ void k_final(float* __restrict__ out, int G) {
    int tid = blockIdx.x * blockDim.x + threadIdx.x;
    int total = 2 * G * HIDC;
    if (tid >= total) return;
    int t = tid / (G * HIDC);
    int rem = tid - t * G * HIDC;
    int g = rem >> 6;
    int c = rem & 63;
    float cnt = fmaxf(g_cntf[g], 1.0f);
    out[tid] = g_sums[(long long)(t * 64 + g) * HIDC + c] / cnt;
}

// ---------------- launch ----------------
extern "C" void kernel_launch(void* const* d_in, const int* in_sizes, int n_in,
                              void* d_out, int out_size) {
    const float* x     = (const float*)d_in[0];
    const int*   ei    = (const int*)d_in[1];
    const int*   batch = (const int*)d_in[2];

    int N = in_sizes[0] / INDIM;   // 50000
    int E = in_sizes[1] / 2;       // 800000
    int G = out_size / (2 * HIDC); // 64

    int wi = 3;
    if (in_sizes[3] == 1) wi = 4;  // num_graphs may be materialized
    const float* W1   = (const float*)d_in[wi + 0];
    const float* b1   = (const float*)d_in[wi + 1];
    const float* Wmu  = (const float*)d_in[wi + 2];
    const float* bmu  = (const float*)d_in[wi + 3];
    const float* Wsig = (const float*)d_in[wi + 4];
    const float* bsig = (const float*)d_in[wi + 5];
    float* out = (float*)d_out;

    const int* src = ei;
    const int* dst = ei + E;

    k_zero<<<(NN + 255) / 256, 256>>>();
    k_deg<<<(E + 255) / 256, 256>>>(dst, E);
    k_scan<<<SCAN_NB, SCAN_BLK>>>(N, E);
    k_fill<<<(E + 255) / 256, 256>>>(src, dst, E);
    k_gemm1<<<(N + 127) / 128, 256>>>(x, W1, N);
    {
        long long t = (long long)N * 32;
        k_gather1<<<(unsigned)((t + 255) / 256), 256>>>(b1, N);
    }
    k_gather2gemm2pool<<<(N + 63) / 64, 256>>>(Wmu, bmu, Wsig, bsig, batch, N);
    k_final<<<(2 * G * HIDC + 255) / 256, 256>>>(out, G);
}

// round 8
// speedup vs baseline: 1.1498x; 1.1498x over previous
#include <cuda_runtime.h>
#include <cuda_fp16.h>
#include <cstdint>

// Problem constants (dataset-fixed shapes).
static constexpr int NN    = 50000;      // nodes
static constexpr int HIDC  = 64;         // hidden/z dim
static constexpr int INDIM = 128;
static constexpr int N64   = NN * HIDC;  // 3,200,000
static constexpr int ECAP  = 1000000;    // edge capacity (dataset: 800000)
static constexpr int SCAN_BLK = 512;
static constexpr int SCAN_NB  = (NN + SCAN_BLK - 1) / SCAN_BLK;  // 98

static constexpr unsigned long long FLAG_AGG = 1ull << 40;
static constexpr unsigned long long FLAG_INC = 2ull << 40;
static constexpr unsigned long long VAL_MASK = (1ull << 40) - 1;

// ---- scratch (device globals; no allocations allowed) ----
__device__ int    g_cnt[NN];
__device__ int    g_offs[NN + 1];
__device__ int    g_cursor[NN];
__device__ unsigned long long g_scanstate[SCAN_NB];
__device__ int2   g_edge[ECAP];       // (src, bitcast(norm)) sorted by dst bucket
__device__ float  g_dinv[NN];
__device__ __half g_XW[N64];          // x @ W1  (fp16 storage, fp32 math)
__device__ __half g_h1[N64];          // ELU(conv1)
__device__ float  g_sums[2 * 64 * 64];
__device__ float  g_cntf[64];

// ---------------- helpers ----------------
__device__ __forceinline__ void red_add_f32x4(float* p, float4 v) {
    asm volatile("red.global.add.v4.f32 [%0], {%1,%2,%3,%4};"
                 :: "l"(p), "f"(v.x), "f"(v.y), "f"(v.z), "f"(v.w) : "memory");
}
__device__ __forceinline__ void red_add_f32(float* p, float v) {
    asm volatile("red.global.add.f32 [%0], %1;" :: "l"(p), "f"(v) : "memory");
}
__device__ __forceinline__ float elu1(float x) { return x > 0.0f ? x : expm1f(x); }
__device__ __forceinline__ float4 elu4(float4 v) {
    v.x = elu1(v.x); v.y = elu1(v.y); v.z = elu1(v.z); v.w = elu1(v.w);
    return v;
}
__device__ __forceinline__ float4 fma4(float4 a, float s, float4 acc) {
    acc.x += a.x * s; acc.y += a.y * s; acc.z += a.z * s; acc.w += a.w * s;
    return acc;
}
__device__ __forceinline__ float4 add4(float4 a, float4 b) {
    a.x += b.x; a.y += b.y; a.z += b.z; a.w += b.w; return a;
}
// accumulate 8 halves (one uint4) scaled by w into acc[8]
__device__ __forceinline__ void fma8h(float* acc, uint4 raw, float w) {
    const __half2* h = reinterpret_cast<const __half2*>(&raw);
#pragma unroll
    for (int j = 0; j < 4; j++) {
        float2 f = __half22float2(h[j]);
        acc[2 * j]     += f.x * w;
        acc[2 * j + 1] += f.y * w;
    }
}
__device__ __forceinline__ uint4 pack8h(const float* a) {
    uint4 out;
    __half2* h = reinterpret_cast<__half2*>(&out);
#pragma unroll
    for (int j = 0; j < 4; j++) h[j] = __floats2half2_rn(a[2 * j], a[2 * j + 1]);
    return out;
}

// CSR gather (fp16 features, fp32 accum): 8 lanes/node, lane owns 8 halves (16B).
// Packed int2 edge records: one 64-bit load per edge per lane.
__device__ __forceinline__ void csr_gather_h(const __half* __restrict__ F,
                                             int node, int c, float* acc) {
    float acc2[8];
#pragma unroll
    for (int j = 0; j < 8; j++) acc2[j] = 0.f;
    int beg = g_offs[node], end = g_offs[node + 1];
    int k = beg;
    for (; k + 4 <= end; k += 4) {
        int2 p0 = g_edge[k + 0];
        int2 p1 = g_edge[k + 1];
        int2 p2 = g_edge[k + 2];
        int2 p3 = g_edge[k + 3];
        uint4 v0 = *reinterpret_cast<const uint4*>(&F[(long long)p0.x * HIDC + c * 8]);
        uint4 v1 = *reinterpret_cast<const uint4*>(&F[(long long)p1.x * HIDC + c * 8]);
        uint4 v2 = *reinterpret_cast<const uint4*>(&F[(long long)p2.x * HIDC + c * 8]);
        uint4 v3 = *reinterpret_cast<const uint4*>(&F[(long long)p3.x * HIDC + c * 8]);
        fma8h(acc,  v0, __int_as_float(p0.y));
        fma8h(acc2, v1, __int_as_float(p1.y));
        fma8h(acc,  v2, __int_as_float(p2.y));
        fma8h(acc2, v3, __int_as_float(p3.y));
    }
    for (; k < end; k++) {
        int2 p = g_edge[k];
        uint4 v = *reinterpret_cast<const uint4*>(&F[(long long)p.x * HIDC + c * 8]);
        fma8h(acc, v, __int_as_float(p.y));
    }
#pragma unroll
    for (int j = 0; j < 8; j++) acc[j] += acc2[j];
}

// ---------------- kernels ----------------

__global__ void k_zero() {
    int i = blockIdx.x * blockDim.x + threadIdx.x;
    if (i < NN) g_cnt[i] = 0;
    if (i < SCAN_NB) g_scanstate[i] = 0ull;
    if (i < 2 * 64 * 64) g_sums[i] = 0.f;
    if (i < 64) g_cntf[i] = 0.f;
}

__global__ void k_deg(const int* __restrict__ dst, int E) {
    int e = blockIdx.x * blockDim.x + threadIdx.x;
    if (e < E) atomicAdd(&g_cnt[dst[e]], 1);
}

// Single-pass scan with warp-parallel decoupled lookback.
// Also computes dinv and initializes cursors.
__global__ __launch_bounds__(SCAN_BLK) void k_scan(int N, int E) {
    __shared__ int wsum[16];
    __shared__ int sh_excl;
    const int tid  = threadIdx.x;
    const int lane = tid & 31;
    const int w    = tid >> 5;
    const int b    = blockIdx.x;
    const int i    = b * SCAN_BLK + tid;

    int v = (i < N) ? g_cnt[i] : 0;
    if (i < N) g_dinv[i] = rsqrtf((float)v + 1.0f);  // +1 self loop

    // in-warp inclusive scan
    int inc = v;
#pragma unroll
    for (int off = 1; off < 32; off <<= 1) {
        int t = __shfl_up_sync(0xFFFFFFFFu, inc, off);
        if (lane >= off) inc += t;
    }
    if (lane == 31) wsum[w] = inc;
    __syncthreads();

    if (w == 0) {
        int wv = (lane < 16) ? wsum[lane] : 0;
        int winc = wv;
#pragma unroll
        for (int off = 1; off < 16; off <<= 1) {
            int t = __shfl_up_sync(0xFFFFFFFFu, winc, off);
            if (lane >= off) winc += t;
        }
        if (lane < 16) wsum[lane] = winc - wv;   // exclusive warp base
        int btot = __shfl_sync(0xFFFFFFFFu, winc, 15);

        if (lane == 0 && b > 0)
            atomicExch(&g_scanstate[b], FLAG_AGG | (unsigned long long)btot);

        int excl = 0;
        if (b > 0) {
            int j = b - 1;
            while (true) {
                int idx = j - lane;
                unsigned long long s = 0;
                if (idx >= 0) {
                    do { s = atomicAdd(&g_scanstate[idx], 0ull); } while (s < FLAG_AGG);
                }
                unsigned incmask = __ballot_sync(0xFFFFFFFFu, idx >= 0 && s >= FLAG_INC);
                if (incmask) {
                    int first = __ffs(incmask) - 1;
                    int val = (lane <= first) ? (int)(s & VAL_MASK) : 0;
#pragma unroll
                    for (int off = 16; off; off >>= 1) val += __shfl_xor_sync(0xFFFFFFFFu, val, off);
                    excl += val;
                    break;
                } else {
                    int val = (idx >= 0) ? (int)(s & VAL_MASK) : 0;
#pragma unroll
                    for (int off = 16; off; off >>= 1) val += __shfl_xor_sync(0xFFFFFFFFu, val, off);
                    excl += val;
                    j -= 32;
                    if (j < 0) break;  // safety (block 0 always publishes INC)
                }
            }
        }
        if (lane == 0) {
            atomicExch(&g_scanstate[b], FLAG_INC | (unsigned long long)(excl + btot));
            sh_excl = excl;
        }
    }
    __syncthreads();

    int my_excl = sh_excl + wsum[w] + inc - v;
    if (i < N) { g_offs[i] = my_excl; g_cursor[i] = my_excl; }
    if (b == 0 && tid == 0) g_offs[N] = E;
}

__global__ void k_fill(const int* __restrict__ src, const int* __restrict__ dst, int E) {
    int e = blockIdx.x * blockDim.x + threadIdx.x;
    if (e < E) {
        int d = dst[e];
        int s = src[e];
        int pos = atomicAdd(&g_cursor[d], 1);
        g_edge[pos] = make_int2(s, __float_as_int(g_dinv[s] * g_dinv[d]));
    }
}

// GEMM1: X[N,128] @ W[128,64] -> g_XW (fp16). 128 rows/block, 256 threads, 8 rows/thread.
__global__ __launch_bounds__(256) void k_gemm1(const float* __restrict__ X,
                                               const float* __restrict__ W, int N) {
    __shared__ float Ws[INDIM * HIDC];
    for (int i = threadIdx.x; i < INDIM * HIDC / 4; i += 256)
        reinterpret_cast<float4*>(Ws)[i] = reinterpret_cast<const float4*>(W)[i];
    __syncthreads();

    const int q  = threadIdx.x & 15;
    const int rg = threadIdx.x >> 4;       // 0..15
    const int row0 = blockIdx.x * 128;

    float4 acc[8];
    int rows[8]; bool valid[8];
#pragma unroll
    for (int rr = 0; rr < 8; rr++) {
        rows[rr] = row0 + rg + 16 * rr;
        valid[rr] = rows[rr] < N;
        acc[rr] = make_float4(0.f, 0.f, 0.f, 0.f);
    }

    for (int k4 = 0; k4 < INDIM / 4; k4++) {
        float4 a[8];
#pragma unroll
        for (int rr = 0; rr < 8; rr++)
            a[rr] = valid[rr]
                ? reinterpret_cast<const float4*>(&X[(long long)rows[rr] * INDIM + k4 * 4])[0]
                : make_float4(0.f, 0.f, 0.f, 0.f);
#pragma unroll
        for (int kk = 0; kk < 4; kk++) {
            float4 w = reinterpret_cast<const float4*>(&Ws[(k4 * 4 + kk) * HIDC + q * 4])[0];
#pragma unroll
            for (int rr = 0; rr < 8; rr++) {
                float av = (&a[rr].x)[kk];
                acc[rr] = fma4(w, av, acc[rr]);
            }
        }
    }
#pragma unroll
    for (int rr = 0; rr < 8; rr++) {
        if (valid[rr]) {
            uint2 p;
            reinterpret_cast<__half2*>(&p)[0] = __floats2half2_rn(acc[rr].x, acc[rr].y);
            reinterpret_cast<__half2*>(&p)[1] = __floats2half2_rn(acc[rr].z, acc[rr].w);
            *reinterpret_cast<uint2*>(&g_XW[(long long)rows[rr] * HIDC + q * 4]) = p;
        }
    }
}

// Layer-1 CSR gather + self-loop + bias + ELU -> g_h1. 8 lanes/node, 8 floats/lane.
__global__ void k_gather1(const float* __restrict__ b1, int N) {
    long long idx = (long long)blockIdx.x * blockDim.x + threadIdx.x;
    if (idx >= (long long)N * 8) return;
    int node = (int)(idx >> 3);
    int c    = (int)(idx & 7);
    float di = g_dinv[node];
    float self = di * di;

    float acc[8];
    {
        uint4 v = *reinterpret_cast<const uint4*>(&g_XW[(long long)node * HIDC + c * 8]);
        const __half2* h = reinterpret_cast<const __half2*>(&v);
#pragma unroll
        for (int j = 0; j < 4; j++) {
            float2 f = __half22float2(h[j]);
            acc[2 * j]     = f.x * self;
            acc[2 * j + 1] = f.y * self;
        }
    }
    csr_gather_h(g_XW, node, c, acc);

#pragma unroll
    for (int j = 0; j < 8; j++) {
        acc[j] += b1[c * 8 + j];
        acc[j] = elu1(acc[j]);
    }
    *reinterpret_cast<uint4*>(&g_h1[(long long)node * HIDC + c * 8]) = pack8h(acc);
}

// Fused layer-2: CSR gather h1 into smem tile (64 nodes), then
// z = tile @ {Wmu,Wsig} + bias, ELU, mean-pool accumulate. 256 threads/block.
__global__ __launch_bounds__(256) void k_gather2gemm2pool(
        const float* __restrict__ Wmu, const float* __restrict__ bmu,
        const float* __restrict__ Wsig, const float* __restrict__ bsig,
        const int* __restrict__ batch, int N) {
    __shared__ float Wms[HIDC * HIDC];
    __shared__ float Wss[HIDC * HIDC];
    __shared__ float tile[64 * HIDC];   // 16 KB
    __shared__ float spool[128];        // 64 mu + 64 sig

    for (int i = threadIdx.x; i < HIDC * HIDC / 4; i += 256) {
        reinterpret_cast<float4*>(Wms)[i] = reinterpret_cast<const float4*>(Wmu)[i];
        reinterpret_cast<float4*>(Wss)[i] = reinterpret_cast<const float4*>(Wsig)[i];
    }
    if (threadIdx.x < 128) spool[threadIdx.x] = 0.f;

    const int row0 = blockIdx.x * 64;

    // ---- Phase A: gather 64 nodes into smem tile (8 lanes/node, 2 nodes/thread) ----
    {
        int c  = threadIdx.x & 7;      // 8-half slice
        int ng = threadIdx.x >> 3;     // 0..31
#pragma unroll
        for (int pp = 0; pp < 2; pp++) {
            int ln = ng + 32 * pp;     // local node 0..63
            int node = row0 + ln;
            float acc[8];
            if (node < N) {
                float di = g_dinv[node];
                float self = di * di;
                uint4 v = *reinterpret_cast<const uint4*>(&g_h1[(long long)node * HIDC + c * 8]);
                const __half2* h = reinterpret_cast<const __half2*>(&v);
#pragma unroll
                for (int j = 0; j < 4; j++) {
                    float2 f = __half22float2(h[j]);
                    acc[2 * j]     = f.x * self;
                    acc[2 * j + 1] = f.y * self;
                }
                csr_gather_h(g_h1, node, c, acc);
            } else {
#pragma unroll
                for (int j = 0; j < 8; j++) acc[j] = 0.f;
            }
            reinterpret_cast<float4*>(&tile[ln * HIDC + c * 8])[0] =
                make_float4(acc[0], acc[1], acc[2], acc[3]);
            reinterpret_cast<float4*>(&tile[ln * HIDC + c * 8 + 4])[0] =
                make_float4(acc[4], acc[5], acc[6], acc[7]);
        }
    }
    __syncthreads();

    // ---- Phase B: dual GEMM from smem + bias + ELU + pool ----
    const int q  = threadIdx.x & 15;
    const int rg = threadIdx.x >> 4;   // 0..15

    float4 am[4], as4[4];
    int rows[4]; bool valid[4];
#pragma unroll
    for (int rr = 0; rr < 4; rr++) {
        rows[rr] = row0 + rg + 16 * rr;
        valid[rr] = rows[rr] < N;
        am[rr]  = make_float4(0.f, 0.f, 0.f, 0.f);
        as4[rr] = make_float4(0.f, 0.f, 0.f, 0.f);
    }

    for (int k4 = 0; k4 < HIDC / 4; k4++) {
        float4 a[4];
#pragma unroll
        for (int rr = 0; rr < 4; rr++)
            a[rr] = reinterpret_cast<const float4*>(&tile[(rg + 16 * rr) * HIDC + k4 * 4])[0];
#pragma unroll
        for (int kk = 0; kk < 4; kk++) {
            float4 wm = reinterpret_cast<const float4*>(&Wms[(k4 * 4 + kk) * HIDC + q * 4])[0];
            float4 ws = reinterpret_cast<const float4*>(&Wss[(k4 * 4 + kk) * HIDC + q * 4])[0];
#pragma unroll
            for (int rr = 0; rr < 4; rr++) {
                float av = (&a[rr].x)[kk];
                am[rr]  = fma4(wm, av, am[rr]);
                as4[rr] = fma4(ws, av, as4[rr]);
            }
        }
    }

    float4 bbm = reinterpret_cast<const float4*>(&bmu[q * 4])[0];
    float4 bbs = reinterpret_cast<const float4*>(&bsig[q * 4])[0];
#pragma unroll
    for (int rr = 0; rr < 4; rr++) {
        am[rr]  = elu4(add4(am[rr], bbm));
        as4[rr] = elu4(add4(as4[rr], bbs));
    }

    int lastRow = min(row0 + 63, N - 1);
    int g0 = batch[row0];
    int g1 = batch[lastRow];

    if (g0 == g1) {
        float4 sm = make_float4(0.f, 0.f, 0.f, 0.f);
        float4 ss = make_float4(0.f, 0.f, 0.f, 0.f);
#pragma unroll
        for (int rr = 0; rr < 4; rr++) {
            if (valid[rr]) { sm = add4(sm, am[rr]); ss = add4(ss, as4[rr]); }
        }
        atomicAdd(&spool[q * 4 + 0], sm.x);
        atomicAdd(&spool[q * 4 + 1], sm.y);
        atomicAdd(&spool[q * 4 + 2], sm.z);
        atomicAdd(&spool[q * 4 + 3], sm.w);
        atomicAdd(&spool[64 + q * 4 + 0], ss.x);
        atomicAdd(&spool[64 + q * 4 + 1], ss.y);
        atomicAdd(&spool[64 + q * 4 + 2], ss.z);
        atomicAdd(&spool[64 + q * 4 + 3], ss.w);
        __syncthreads();
        if (threadIdx.x < 32) {
            int half = threadIdx.x >> 4;
            int cc   = threadIdx.x & 15;
            float4 v = reinterpret_cast<const float4*>(&spool[half * 64 + cc * 4])[0];
            red_add_f32x4(&g_sums[(long long)(half * 64 + g0) * HIDC + cc * 4], v);
        }
        if (threadIdx.x == 0) {
            int cnt = min(N - row0, 64);
            red_add_f32(&g_cntf[g0], (float)cnt);
        }
    } else {
#pragma unroll
        for (int rr = 0; rr < 4; rr++) {
            if (!valid[rr]) continue;
            int g = batch[rows[rr]];
            red_add_f32x4(&g_sums[(long long)(0 * 64 + g) * HIDC + q * 4], am[rr]);
            red_add_f32x4(&g_sums[(long long)(1 * 64 + g) * HIDC + q * 4], as4[rr]);
            if (q == 0) red_add_f32(&g_cntf[g], 1.0f);
        }
    }
}

// Final: divide by counts, write [z_mu ; z_sigma] to d_out.
__global__ void k_final(float* __restrict__ out, int G) {
    int tid = blockIdx.x * blockDim.x + threadIdx.x;
    int total = 2 * G * HIDC;
    if (tid >= total) return;
    int t = tid / (G * HIDC);
    int rem = tid - t * G * HIDC;
    int g = rem >> 6;
    int c = rem & 63;
    float cnt = fmaxf(g_cntf[g], 1.0f);
    out[tid] = g_sums[(long long)(t * 64 + g) * HIDC + c] / cnt;
}

// ---------------- launch ----------------
extern "C" void kernel_launch(void* const* d_in, const int* in_sizes, int n_in,
                              void* d_out, int out_size) {
    const float* x     = (const float*)d_in[0];
    const int*   ei    = (const int*)d_in[1];
    const int*   batch = (const int*)d_in[2];

    int N = in_sizes[0] / INDIM;   // 50000
    int E = in_sizes[1] / 2;       // 800000
    int G = out_size / (2 * HIDC); // 64

    int wi = 3;
    if (in_sizes[3] == 1) wi = 4;  // num_graphs may be materialized
    const float* W1   = (const float*)d_in[wi + 0];
    const float* b1   = (const float*)d_in[wi + 1];
    const float* Wmu  = (const float*)d_in[wi + 2];
    const float* bmu  = (const float*)d_in[wi + 3];
    const float* Wsig = (const float*)d_in[wi + 4];
    const float* bsig = (const float*)d_in[wi + 5];
    float* out = (float*)d_out;

    const int* src = ei;
    const int* dst = ei + E;

    k_zero<<<(NN + 255) / 256, 256>>>();
    k_deg<<<(E + 255) / 256, 256>>>(dst, E);
    k_scan<<<SCAN_NB, SCAN_BLK>>>(N, E);
    k_fill<<<(E + 255) / 256, 256>>>(src, dst, E);
    k_gemm1<<<(N + 127) / 128, 256>>>(x, W1, N);
    {
        long long t = (long long)N * 8;
        k_gather1<<<(unsigned)((t + 255) / 256), 256>>>(b1, N);
    }
    k_gather2gemm2pool<<<(N + 63) / 64, 256>>>(Wmu, bmu, Wsig, bsig, batch, N);
    k_final<<<(2 * G * HIDC + 255) / 256, 256>>>(out, G);
}

// round 9
// speedup vs baseline: 1.3442x; 1.1691x over previous
#include <cuda_runtime.h>
#include <cuda_fp16.h>
#include <cstdint>

// Problem constants (dataset-fixed shapes).
static constexpr int NN    = 50000;      // nodes
static constexpr int HIDC  = 64;         // hidden/z dim
static constexpr int INDIM = 128;
static constexpr int N64   = NN * HIDC;  // 3,200,000
static constexpr int ECAP  = 1000000;    // edge capacity (dataset: 800000)
static constexpr int SCAN_BLK = 512;
static constexpr int SCAN_NB  = (NN + SCAN_BLK - 1) / SCAN_BLK;  // 98

// ---- scratch (device globals; no allocations allowed) ----
__device__ int    g_cnt[NN];
__device__ int    g_offs[NN + 1];
__device__ int    g_cursor[NN];
__device__ int    g_bsum[SCAN_NB];
__device__ int    g_srcs[ECAP];
__device__ float  g_w[ECAP];          // per-edge norm = dinv[s]*dinv[d]
__device__ float  g_dinv[NN];
__device__ __half g_XW[N64];          // x @ W1  (fp16 storage, fp32 math)
__device__ __half g_h1[N64];          // ELU(conv1)
__device__ float  g_sums[2 * 64 * 64];
__device__ float  g_cntf[64];

// ---------------- helpers ----------------
__device__ __forceinline__ void red_add_f32x4(float* p, float4 v) {
    asm volatile("red.global.add.v4.f32 [%0], {%1,%2,%3,%4};"
                 :: "l"(p), "f"(v.x), "f"(v.y), "f"(v.z), "f"(v.w) : "memory");
}
__device__ __forceinline__ void red_add_f32(float* p, float v) {
    asm volatile("red.global.add.f32 [%0], %1;" :: "l"(p), "f"(v) : "memory");
}
__device__ __forceinline__ float elu1(float x) { return x > 0.0f ? x : expm1f(x); }
__device__ __forceinline__ float4 elu4(float4 v) {
    v.x = elu1(v.x); v.y = elu1(v.y); v.z = elu1(v.z); v.w = elu1(v.w);
    return v;
}
__device__ __forceinline__ float4 fma4(float4 a, float s, float4 acc) {
    acc.x += a.x * s; acc.y += a.y * s; acc.z += a.z * s; acc.w += a.w * s;
    return acc;
}
__device__ __forceinline__ float4 add4(float4 a, float4 b) {
    a.x += b.x; a.y += b.y; a.z += b.z; a.w += b.w; return a;
}
// accumulate 8 halves (one uint4) scaled by w into acc[8]
__device__ __forceinline__ void fma8h(float* acc, uint4 raw, float w) {
    const __half2* h = reinterpret_cast<const __half2*>(&raw);
#pragma unroll
    for (int j = 0; j < 4; j++) {
        float2 f = __half22float2(h[j]);
        acc[2 * j]     += f.x * w;
        acc[2 * j + 1] += f.y * w;
    }
}
__device__ __forceinline__ uint4 pack8h(const float* a) {
    uint4 out;
    __half2* h = reinterpret_cast<__half2*>(&out);
#pragma unroll
    for (int j = 0; j < 4; j++) h[j] = __floats2half2_rn(a[2 * j], a[2 * j + 1]);
    return out;
}

// CSR gather (fp16 features, fp32 accum): 8 lanes/node, lane owns 8 halves (16B).
__device__ __forceinline__ void csr_gather_h(const __half* __restrict__ F,
                                             int node, int c, float* acc) {
    float acc2[8];
#pragma unroll
    for (int j = 0; j < 8; j++) acc2[j] = 0.f;
    int beg = g_offs[node], end = g_offs[node + 1];
    int k = beg;
    for (; k + 4 <= end; k += 4) {
        int s0 = g_srcs[k + 0], s1 = g_srcs[k + 1];
        int s2 = g_srcs[k + 2], s3 = g_srcs[k + 3];
        float w0 = g_w[k + 0], w1 = g_w[k + 1];
        float w2 = g_w[k + 2], w3 = g_w[k + 3];
        uint4 v0 = *reinterpret_cast<const uint4*>(&F[(long long)s0 * HIDC + c * 8]);
        uint4 v1 = *reinterpret_cast<const uint4*>(&F[(long long)s1 * HIDC + c * 8]);
        uint4 v2 = *reinterpret_cast<const uint4*>(&F[(long long)s2 * HIDC + c * 8]);
        uint4 v3 = *reinterpret_cast<const uint4*>(&F[(long long)s3 * HIDC + c * 8]);
        fma8h(acc,  v0, w0);
        fma8h(acc2, v1, w1);
        fma8h(acc,  v2, w2);
        fma8h(acc2, v3, w3);
    }
    for (; k < end; k++) {
        int s = g_srcs[k];
        float w = g_w[k];
        uint4 v = *reinterpret_cast<const uint4*>(&F[(long long)s * HIDC + c * 8]);
        fma8h(acc, v, w);
    }
#pragma unroll
    for (int j = 0; j < 8; j++) acc[j] += acc2[j];
}

// ---------------- kernels ----------------

__global__ void k_zero() {
    int i = blockIdx.x * blockDim.x + threadIdx.x;
    if (i < NN) g_cnt[i] = 0;
    if (i < 2 * 64 * 64) g_sums[i] = 0.f;
    if (i < 64) g_cntf[i] = 0.f;
}

__global__ void k_deg(const int* __restrict__ dst, int E) {
    int e = blockIdx.x * blockDim.x + threadIdx.x;
    if (e < E) atomicAdd(&g_cnt[dst[e]], 1);
}

// block-local exclusive scan of counts; also dinv and per-block sums.
__global__ void k_scan1(int N) {
    __shared__ int sh[SCAN_BLK];
    int tid = threadIdx.x;
    int i = blockIdx.x * SCAN_BLK + tid;
    int v = (i < N) ? g_cnt[i] : 0;
    if (i < N) g_dinv[i] = rsqrtf((float)v + 1.0f);  // +1 self loop
    sh[tid] = v;
    __syncthreads();
#pragma unroll
    for (int off = 1; off < SCAN_BLK; off <<= 1) {
        int t = (tid >= off) ? sh[tid - off] : 0;
        __syncthreads();
        sh[tid] += t;
        __syncthreads();
    }
    if (i < N) g_offs[i] = sh[tid] - v;
    if (tid == SCAN_BLK - 1) g_bsum[blockIdx.x] = sh[tid];
}

// Adds cross-block prefix (parallel Hillis-Steele over the 98 partials).
__global__ void k_scan3(int N, int E) {
    __shared__ int sb[128];
    int tid = threadIdx.x;
    if (tid < 128) sb[tid] = (tid < SCAN_NB) ? g_bsum[tid] : 0;
    __syncthreads();
#pragma unroll
    for (int off = 1; off < 128; off <<= 1) {
        int t = (tid < 128 && tid >= off) ? sb[tid - off] : 0;
        __syncthreads();
        if (tid < 128) sb[tid] += t;
        __syncthreads();
    }
    int i = blockIdx.x * blockDim.x + tid;
    if (i < N) {
        int blk = i / SCAN_BLK;
        int base = (blk == 0) ? 0 : sb[blk - 1];   // exclusive prefix
        int o = g_offs[i] + base;
        g_offs[i] = o;
        g_cursor[i] = o;
    }
    if (i == 0) g_offs[N] = E;
}

__global__ void k_fill(const int* __restrict__ src, const int* __restrict__ dst, int E) {
    int e = blockIdx.x * blockDim.x + threadIdx.x;
    if (e < E) {
        int d = dst[e];
        int s = src[e];
        int pos = atomicAdd(&g_cursor[d], 1);
        g_srcs[pos] = s;
        g_w[pos] = g_dinv[s] * g_dinv[d];
    }
}

// GEMM1: X[N,128] @ W[128,64] -> g_XW (fp16). 128 rows/block, 256 threads, 8 rows/thread.
__global__ __launch_bounds__(256) void k_gemm1(const float* __restrict__ X,
                                               const float* __restrict__ W, int N) {
    __shared__ float Ws[INDIM * HIDC];
    for (int i = threadIdx.x; i < INDIM * HIDC / 4; i += 256)
        reinterpret_cast<float4*>(Ws)[i] = reinterpret_cast<const float4*>(W)[i];
    __syncthreads();

    const int q  = threadIdx.x & 15;
    const int rg = threadIdx.x >> 4;       // 0..15
    const int row0 = blockIdx.x * 128;

    float4 acc[8];
    int rows[8]; bool valid[8];
#pragma unroll
    for (int rr = 0; rr < 8; rr++) {
        rows[rr] = row0 + rg + 16 * rr;
        valid[rr] = rows[rr] < N;
        acc[rr] = make_float4(0.f, 0.f, 0.f, 0.f);
    }

    for (int k4 = 0; k4 < INDIM / 4; k4++) {
        float4 a[8];
#pragma unroll
        for (int rr = 0; rr < 8; rr++)
            a[rr] = valid[rr]
                ? reinterpret_cast<const float4*>(&X[(long long)rows[rr] * INDIM + k4 * 4])[0]
                : make_float4(0.f, 0.f, 0.f, 0.f);
#pragma unroll
        for (int kk = 0; kk < 4; kk++) {
            float4 w = reinterpret_cast<const float4*>(&Ws[(k4 * 4 + kk) * HIDC + q * 4])[0];
#pragma unroll
            for (int rr = 0; rr < 8; rr++) {
                float av = (&a[rr].x)[kk];
                acc[rr] = fma4(w, av, acc[rr]);
            }
        }
    }
#pragma unroll
    for (int rr = 0; rr < 8; rr++) {
        if (valid[rr]) {
            uint2 p;
            reinterpret_cast<__half2*>(&p)[0] = __floats2half2_rn(acc[rr].x, acc[rr].y);
            reinterpret_cast<__half2*>(&p)[1] = __floats2half2_rn(acc[rr].z, acc[rr].w);
            *reinterpret_cast<uint2*>(&g_XW[(long long)rows[rr] * HIDC + q * 4]) = p;
        }
    }
}

// Layer-1 CSR gather + self-loop + bias + ELU -> g_h1. 8 lanes/node, 8 floats/lane.
__global__ void k_gather1(const float* __restrict__ b1, int N) {
    long long idx = (long long)blockIdx.x * blockDim.x + threadIdx.x;
    if (idx >= (long long)N * 8) return;
    int node = (int)(idx >> 3);
    int c    = (int)(idx & 7);
    float di = g_dinv[node];
    float self = di * di;

    float acc[8];
    {
        uint4 v = *reinterpret_cast<const uint4*>(&g_XW[(long long)node * HIDC + c * 8]);
        const __half2* h = reinterpret_cast<const __half2*>(&v);
#pragma unroll
        for (int j = 0; j < 4; j++) {
            float2 f = __half22float2(h[j]);
            acc[2 * j]     = f.x * self;
            acc[2 * j + 1] = f.y * self;
        }
    }
    csr_gather_h(g_XW, node, c, acc);

#pragma unroll
    for (int j = 0; j < 8; j++) {
        acc[j] += b1[c * 8 + j];
        acc[j] = elu1(acc[j]);
    }
    *reinterpret_cast<uint4*>(&g_h1[(long long)node * HIDC + c * 8]) = pack8h(acc);
}

// Fused layer-2: CSR gather h1 into smem tile (64 nodes), then
// z = tile @ {Wmu,Wsig} + bias, ELU, mean-pool accumulate. 256 threads/block.
__global__ __launch_bounds__(256) void k_gather2gemm2pool(
        const float* __restrict__ Wmu, const float* __restrict__ bmu,
        const float* __restrict__ Wsig, const float* __restrict__ bsig,
        const int* __restrict__ batch, int N) {
    __shared__ float Wms[HIDC * HIDC];
    __shared__ float Wss[HIDC * HIDC];
    __shared__ float tile[64 * HIDC];   // 16 KB
    __shared__ float spool[128];        // 64 mu + 64 sig

    for (int i = threadIdx.x; i < HIDC * HIDC / 4; i += 256) {
        reinterpret_cast<float4*>(Wms)[i] = reinterpret_cast<const float4*>(Wmu)[i];
        reinterpret_cast<float4*>(Wss)[i] = reinterpret_cast<const float4*>(Wsig)[i];
    }
    if (threadIdx.x < 128) spool[threadIdx.x] = 0.f;

    const int row0 = blockIdx.x * 64;

    // ---- Phase A: gather 64 nodes into smem tile (8 lanes/node, 2 nodes/thread) ----
    {
        int c  = threadIdx.x & 7;      // 8-half slice
        int ng = threadIdx.x >> 3;     // 0..31
#pragma unroll
        for (int pp = 0; pp < 2; pp++) {
            int ln = ng + 32 * pp;     // local node 0..63
            int node = row0 + ln;
            float acc[8];
            if (node < N) {
                float di = g_dinv[node];
                float self = di * di;
                uint4 v = *reinterpret_cast<const uint4*>(&g_h1[(long long)node * HIDC + c * 8]);
                const __half2* h = reinterpret_cast<const __half2*>(&v);
#pragma unroll
                for (int j = 0; j < 4; j++) {
                    float2 f = __half22float2(h[j]);
                    acc[2 * j]     = f.x * self;
                    acc[2 * j + 1] = f.y * self;
                }
                csr_gather_h(g_h1, node, c, acc);
            } else {
#pragma unroll
                for (int j = 0; j < 8; j++) acc[j] = 0.f;
            }
            reinterpret_cast<float4*>(&tile[ln * HIDC + c * 8])[0] =
                make_float4(acc[0], acc[1], acc[2], acc[3]);
            reinterpret_cast<float4*>(&tile[ln * HIDC + c * 8 + 4])[0] =
                make_float4(acc[4], acc[5], acc[6], acc[7]);
        }
    }
    __syncthreads();

    // ---- Phase B: dual GEMM from smem + bias + ELU + pool ----
    const int q  = threadIdx.x & 15;
    const int rg = threadIdx.x >> 4;   // 0..15

    float4 am[4], as4[4];
    int rows[4]; bool valid[4];
#pragma unroll
    for (int rr = 0; rr < 4; rr++) {
        rows[rr] = row0 + rg + 16 * rr;
        valid[rr] = rows[rr] < N;
        am[rr]  = make_float4(0.f, 0.f, 0.f, 0.f);
        as4[rr] = make_float4(0.f, 0.f, 0.f, 0.f);
    }

    for (int k4 = 0; k4 < HIDC / 4; k4++) {
        float4 a[4];
#pragma unroll
        for (int rr = 0; rr < 4; rr++)
            a[rr] = reinterpret_cast<const float4*>(&tile[(rg + 16 * rr) * HIDC + k4 * 4])[0];
#pragma unroll
        for (int kk = 0; kk < 4; kk++) {
            float4 wm = reinterpret_cast<const float4*>(&Wms[(k4 * 4 + kk) * HIDC + q * 4])[0];
            float4 ws = reinterpret_cast<const float4*>(&Wss[(k4 * 4 + kk) * HIDC + q * 4])[0];
#pragma unroll
            for (int rr = 0; rr < 4; rr++) {
                float av = (&a[rr].x)[kk];
                am[rr]  = fma4(wm, av, am[rr]);
                as4[rr] = fma4(ws, av, as4[rr]);
            }
        }
    }

    float4 bbm = reinterpret_cast<const float4*>(&bmu[q * 4])[0];
    float4 bbs = reinterpret_cast<const float4*>(&bsig[q * 4])[0];
#pragma unroll
    for (int rr = 0; rr < 4; rr++) {
        am[rr]  = elu4(add4(am[rr], bbm));
        as4[rr] = elu4(add4(as4[rr], bbs));
    }

    int lastRow = min(row0 + 63, N - 1);
    int g0 = batch[row0];
    int g1 = batch[lastRow];

    if (g0 == g1) {
        float4 sm = make_float4(0.f, 0.f, 0.f, 0.f);
        float4 ss = make_float4(0.f, 0.f, 0.f, 0.f);
#pragma unroll
        for (int rr = 0; rr < 4; rr++) {
            if (valid[rr]) { sm = add4(sm, am[rr]); ss = add4(ss, as4[rr]); }
        }
        atomicAdd(&spool[q * 4 + 0], sm.x);
        atomicAdd(&spool[q * 4 + 1], sm.y);
        atomicAdd(&spool[q * 4 + 2], sm.z);
        atomicAdd(&spool[q * 4 + 3], sm.w);
        atomicAdd(&spool[64 + q * 4 + 0], ss.x);
        atomicAdd(&spool[64 + q * 4 + 1], ss.y);
        atomicAdd(&spool[64 + q * 4 + 2], ss.z);
        atomicAdd(&spool[64 + q * 4 + 3], ss.w);
        __syncthreads();
        if (threadIdx.x < 32) {
            int half = threadIdx.x >> 4;
            int cc   = threadIdx.x & 15;
            float4 v = reinterpret_cast<const float4*>(&spool[half * 64 + cc * 4])[0];
            red_add_f32x4(&g_sums[(long long)(half * 64 + g0) * HIDC + cc * 4], v);
        }
        if (threadIdx.x == 0) {
            int cnt = min(N - row0, 64);
            red_add_f32(&g_cntf[g0], (float)cnt);
        }
    } else {
#pragma unroll
        for (int rr = 0; rr < 4; rr++) {
            if (!valid[rr]) continue;
            int g = batch[rows[rr]];
            red_add_f32x4(&g_sums[(long long)(0 * 64 + g) * HIDC + q * 4], am[rr]);
            red_add_f32x4(&g_sums[(long long)(1 * 64 + g) * HIDC + q * 4], as4[rr]);
            if (q == 0) red_add_f32(&g_cntf[g], 1.0f);
        }
    }
}

// Final: divide by counts, write [z_mu ; z_sigma] to d_out.
__global__ void k_final(float* __restrict__ out, int G) {
    int tid = blockIdx.x * blockDim.x + threadIdx.x;
    int total = 2 * G * HIDC;
    if (tid >= total) return;
    int t = tid / (G * HIDC);
    int rem = tid - t * G * HIDC;
    int g = rem >> 6;
    int c = rem & 63;
    float cnt = fmaxf(g_cntf[g], 1.0f);
    out[tid] = g_sums[(long long)(t * 64 + g) * HIDC + c] / cnt;
}

// ---------------- launch ----------------
extern "C" void kernel_launch(void* const* d_in, const int* in_sizes, int n_in,
                              void* d_out, int out_size) {
    const float* x     = (const float*)d_in[0];
    const int*   ei    = (const int*)d_in[1];
    const int*   batch = (const int*)d_in[2];

    int N = in_sizes[0] / INDIM;   // 50000
    int E = in_sizes[1] / 2;       // 800000
    int G = out_size / (2 * HIDC); // 64

    int wi = 3;
    if (in_sizes[3] == 1) wi = 4;  // num_graphs may be materialized
    const float* W1   = (const float*)d_in[wi + 0];
    const float* b1   = (const float*)d_in[wi + 1];
    const float* Wmu  = (const float*)d_in[wi + 2];
    const float* bmu  = (const float*)d_in[wi + 3];
    const float* Wsig = (const float*)d_in[wi + 4];
    const float* bsig = (const float*)d_in[wi + 5];
    float* out = (float*)d_out;

    const int* src = ei;
    const int* dst = ei + E;

    // Fork-join: CSR build chain on the main (capture) stream, gemm1 on a
    // side stream — they share no data until k_gather1.
    cudaStream_t s2;
    cudaStreamCreateWithFlags(&s2, cudaStreamNonBlocking);
    cudaEvent_t evF, evJ;
    cudaEventCreateWithFlags(&evF, cudaEventDisableTiming);
    cudaEventCreateWithFlags(&evJ, cudaEventDisableTiming);

    cudaEventRecord(evF, 0);
    cudaStreamWaitEvent(s2, evF, 0);
    k_gemm1<<<(N + 127) / 128, 256, 0, s2>>>(x, W1, N);   // branch B
    cudaEventRecord(evJ, s2);

    // branch A: CSR build
    k_zero<<<(NN + 255) / 256, 256>>>();
    k_deg<<<(E + 255) / 256, 256>>>(dst, E);
    k_scan1<<<SCAN_NB, SCAN_BLK>>>(N);
    k_scan3<<<(N + 255) / 256, 256>>>(N, E);
    k_fill<<<(E + 255) / 256, 256>>>(src, dst, E);

    cudaStreamWaitEvent(0, evJ, 0);   // join before gather1

    {
        long long t = (long long)N * 8;
        k_gather1<<<(unsigned)((t + 255) / 256), 256>>>(b1, N);
    }
    k_gather2gemm2pool<<<(N + 63) / 64, 256>>>(Wmu, bmu, Wsig, bsig, batch, N);
    k_final<<<(2 * G * HIDC + 255) / 256, 256>>>(out, G);

    cudaEventDestroy(evF);
    cudaEventDestroy(evJ);
    cudaStreamDestroy(s2);
}

// round 11
// speedup vs baseline: 1.3703x; 1.0194x over previous
#include <cuda_runtime.h>
#include <cuda_fp16.h>
#include <cstdint>

// Problem constants (dataset-fixed shapes).
static constexpr int NN    = 50000;      // nodes
static constexpr int HIDC  = 64;         // hidden/z dim
static constexpr int INDIM = 128;
static constexpr int N64   = NN * HIDC;  // 3,200,000
static constexpr int ECAP  = 1000000;    // edge capacity (dataset: 800000)
static constexpr int SCAN_BLK = 512;
static constexpr int SCAN_NB  = (NN + SCAN_BLK - 1) / SCAN_BLK;  // 98

// ---- scratch (device globals; no allocations allowed) ----
__device__ int    g_cnt[NN];
__device__ int    g_offs[NN + 1];
__device__ int    g_cursor[NN];
__device__ int    g_bsum[SCAN_NB];
__device__ int2   g_edge[ECAP];       // (src, bitcast(norm)) bucketed by dst
__device__ float  g_dinv[NN];
__device__ __half g_XW[N64];          // x @ W1  (fp16 storage, fp32 math)
__device__ __half g_h1[N64];          // ELU(conv1)
__device__ float  g_sums[2 * 64 * 64];
__device__ float  g_cntf[64];

// ---------------- helpers ----------------
__device__ __forceinline__ void red_add_f32x4(float* p, float4 v) {
    asm volatile("red.global.add.v4.f32 [%0], {%1,%2,%3,%4};"
                 :: "l"(p), "f"(v.x), "f"(v.y), "f"(v.z), "f"(v.w) : "memory");
}
__device__ __forceinline__ void red_add_f32(float* p, float v) {
    asm volatile("red.global.add.f32 [%0], %1;" :: "l"(p), "f"(v) : "memory");
}
__device__ __forceinline__ float elu1(float x) { return x > 0.0f ? x : expm1f(x); }
__device__ __forceinline__ float4 elu4(float4 v) {
    v.x = elu1(v.x); v.y = elu1(v.y); v.z = elu1(v.z); v.w = elu1(v.w);
    return v;
}
__device__ __forceinline__ float4 fma4(float4 a, float s, float4 acc) {
    acc.x += a.x * s; acc.y += a.y * s; acc.z += a.z * s; acc.w += a.w * s;
    return acc;
}
__device__ __forceinline__ float4 add4(float4 a, float4 b) {
    a.x += b.x; a.y += b.y; a.z += b.z; a.w += b.w; return a;
}
// accumulate 8 halves (one uint4) scaled by w into acc[8]
__device__ __forceinline__ void fma8h(float* acc, uint4 raw, float w) {
    const __half2* h = reinterpret_cast<const __half2*>(&raw);
#pragma unroll
    for (int j = 0; j < 4; j++) {
        float2 f = __half22float2(h[j]);
        acc[2 * j]     += f.x * w;
        acc[2 * j + 1] += f.y * w;
    }
}
__device__ __forceinline__ uint4 pack8h(const float* a) {
    uint4 out;
    __half2* h = reinterpret_cast<__half2*>(&out);
#pragma unroll
    for (int j = 0; j < 4; j++) h[j] = __floats2half2_rn(a[2 * j], a[2 * j + 1]);
    return out;
}

// CSR gather (fp16 features, fp32 accum): 8 lanes/node, lane owns 8 halves (16B).
// Packed int2 edge records: one 64-bit load per edge per lane.
__device__ __forceinline__ void csr_gather_h(const __half* __restrict__ F,
                                             int node, int c, float* acc) {
    float acc2[8];
#pragma unroll
    for (int j = 0; j < 8; j++) acc2[j] = 0.f;
    int beg = g_offs[node], end = g_offs[node + 1];
    int k = beg;
    for (; k + 4 <= end; k += 4) {
        int2 p0 = g_edge[k + 0];
        int2 p1 = g_edge[k + 1];
        int2 p2 = g_edge[k + 2];
        int2 p3 = g_edge[k + 3];
        uint4 v0 = *reinterpret_cast<const uint4*>(&F[(long long)p0.x * HIDC + c * 8]);
        uint4 v1 = *reinterpret_cast<const uint4*>(&F[(long long)p1.x * HIDC + c * 8]);
        uint4 v2 = *reinterpret_cast<const uint4*>(&F[(long long)p2.x * HIDC + c * 8]);
        uint4 v3 = *reinterpret_cast<const uint4*>(&F[(long long)p3.x * HIDC + c * 8]);
        fma8h(acc,  v0, __int_as_float(p0.y));
        fma8h(acc2, v1, __int_as_float(p1.y));
        fma8h(acc,  v2, __int_as_float(p2.y));
        fma8h(acc2, v3, __int_as_float(p3.y));
    }
    for (; k < end; k++) {
        int2 p = g_edge[k];
        uint4 v = *reinterpret_cast<const uint4*>(&F[(long long)p.x * HIDC + c * 8]);
        fma8h(acc, v, __int_as_float(p.y));
    }
#pragma unroll
    for (int j = 0; j < 8; j++) acc[j] += acc2[j];
}

// ---------------- kernels ----------------

__global__ void k_zero() {
    int i = blockIdx.x * blockDim.x + threadIdx.x;
    if (i < NN) g_cnt[i] = 0;
    if (i < 2 * 64 * 64) g_sums[i] = 0.f;
    if (i < 64) g_cntf[i] = 0.f;
}

__global__ void k_deg(const int* __restrict__ dst, int E) {
    int e = blockIdx.x * blockDim.x + threadIdx.x;
    if (e < E) atomicAdd(&g_cnt[dst[e]], 1);
}

// block-local exclusive scan of counts (warp-shuffle); also dinv + per-block sums.
__global__ __launch_bounds__(SCAN_BLK) void k_scan1(int N) {
    __shared__ int wsum[16];
    const int tid  = threadIdx.x;
    const int lane = tid & 31;
    const int w    = tid >> 5;
    const int i    = blockIdx.x * SCAN_BLK + tid;

    int v = (i < N) ? g_cnt[i] : 0;
    if (i < N) g_dinv[i] = rsqrtf((float)v + 1.0f);  // +1 self loop

    int inc = v;
#pragma unroll
    for (int off = 1; off < 32; off <<= 1) {
        int t = __shfl_up_sync(0xFFFFFFFFu, inc, off);
        if (lane >= off) inc += t;
    }
    if (lane == 31) wsum[w] = inc;
    __syncthreads();
    if (w == 0) {
        int wv = (lane < 16) ? wsum[lane] : 0;
        int winc = wv;
#pragma unroll
        for (int off = 1; off < 16; off <<= 1) {
            int t = __shfl_up_sync(0xFFFFFFFFu, winc, off);
            if (lane >= off) winc += t;
        }
        if (lane < 16) wsum[lane] = winc - wv;     // exclusive warp base
        if (lane == 15) g_bsum[blockIdx.x] = winc; // block total
    }
    __syncthreads();

    if (i < N) g_offs[i] = wsum[w] + inc - v;
}

// Adds cross-block prefix (parallel Hillis-Steele over the 98 partials).
__global__ void k_scan3(int N, int E) {
    __shared__ int sb[128];
    int tid = threadIdx.x;
    if (tid < 128) sb[tid] = (tid < SCAN_NB) ? g_bsum[tid] : 0;
    __syncthreads();
#pragma unroll
    for (int off = 1; off < 128; off <<= 1) {
        int t = (tid < 128 && tid >= off) ? sb[tid - off] : 0;
        __syncthreads();
        if (tid < 128) sb[tid] += t;
        __syncthreads();
    }
    int i = blockIdx.x * blockDim.x + tid;
    if (i < N) {
        int blk = i / SCAN_BLK;
        int base = (blk == 0) ? 0 : sb[blk - 1];   // exclusive prefix
        int o = g_offs[i] + base;
        g_offs[i] = o;
        g_cursor[i] = o;
    }
    if (i == 0) g_offs[N] = E;
}

__global__ void k_fill(const int* __restrict__ src, const int* __restrict__ dst, int E) {
    int e = blockIdx.x * blockDim.x + threadIdx.x;
    if (e < E) {
        int d = dst[e];
        int s = src[e];
        int pos = atomicAdd(&g_cursor[d], 1);
        g_edge[pos] = make_int2(s, __float_as_int(g_dinv[s] * g_dinv[d]));
    }
}

// GEMM1: X[N,128] @ W[128,64] -> g_XW (fp16). 128 rows/block, 256 threads, 8 rows/thread.
__global__ __launch_bounds__(256) void k_gemm1(const float* __restrict__ X,
                                               const float* __restrict__ W, int N) {
    __shared__ float Ws[INDIM * HIDC];
    for (int i = threadIdx.x; i < INDIM * HIDC / 4; i += 256)
        reinterpret_cast<float4*>(Ws)[i] = reinterpret_cast<const float4*>(W)[i];
    __syncthreads();

    const int q  = threadIdx.x & 15;
    const int rg = threadIdx.x >> 4;       // 0..15
    const int row0 = blockIdx.x * 128;

    float4 acc[8];
    int rows[8]; bool valid[8];
#pragma unroll
    for (int rr = 0; rr < 8; rr++) {
        rows[rr] = row0 + rg + 16 * rr;
        valid[rr] = rows[rr] < N;
        acc[rr] = make_float4(0.f, 0.f, 0.f, 0.f);
    }

    for (int k4 = 0; k4 < INDIM / 4; k4++) {
        float4 a[8];
#pragma unroll
        for (int rr = 0; rr < 8; rr++)
            a[rr] = valid[rr]
                ? reinterpret_cast<const float4*>(&X[(long long)rows[rr] * INDIM + k4 * 4])[0]
                : make_float4(0.f, 0.f, 0.f, 0.f);
#pragma unroll
        for (int kk = 0; kk < 4; kk++) {
            float4 w = reinterpret_cast<const float4*>(&Ws[(k4 * 4 + kk) * HIDC + q * 4])[0];
#pragma unroll
            for (int rr = 0; rr < 8; rr++) {
                float av = (&a[rr].x)[kk];
                acc[rr] = fma4(w, av, acc[rr]);
            }
        }
    }
#pragma unroll
    for (int rr = 0; rr < 8; rr++) {
        if (valid[rr]) {
            uint2 p;
            reinterpret_cast<__half2*>(&p)[0] = __floats2half2_rn(acc[rr].x, acc[rr].y);
            reinterpret_cast<__half2*>(&p)[1] = __floats2half2_rn(acc[rr].z, acc[rr].w);
            *reinterpret_cast<uint2*>(&g_XW[(long long)rows[rr] * HIDC + q * 4]) = p;
        }
    }
}

// Layer-1 CSR gather + self-loop + bias + ELU -> g_h1. 8 lanes/node, 8 floats/lane.
__global__ void k_gather1(const float* __restrict__ b1, int N) {
    long long idx = (long long)blockIdx.x * blockDim.x + threadIdx.x;
    if (idx >= (long long)N * 8) return;
    int node = (int)(idx >> 3);
    int c    = (int)(idx & 7);
    float di = g_dinv[node];
    float self = di * di;

    float acc[8];
    {
        uint4 v = *reinterpret_cast<const uint4*>(&g_XW[(long long)node * HIDC + c * 8]);
        const __half2* h = reinterpret_cast<const __half2*>(&v);
#pragma unroll
        for (int j = 0; j < 4; j++) {
            float2 f = __half22float2(h[j]);
            acc[2 * j]     = f.x * self;
            acc[2 * j + 1] = f.y * self;
        }
    }
    csr_gather_h(g_XW, node, c, acc);

#pragma unroll
    for (int j = 0; j < 8; j++) {
        acc[j] += b1[c * 8 + j];
        acc[j] = elu1(acc[j]);
    }
    *reinterpret_cast<uint4*>(&g_h1[(long long)node * HIDC + c * 8]) = pack8h(acc);
}

// Fused layer-2: CSR gather h1 into smem tile (64 nodes), then
// z = tile @ {Wmu,Wsig} + bias, ELU, mean-pool accumulate. 256 threads/block.
__global__ __launch_bounds__(256) void k_gather2gemm2pool(
        const float* __restrict__ Wmu, const float* __restrict__ bmu,
        const float* __restrict__ Wsig, const float* __restrict__ bsig,
        const int* __restrict__ batch, int N) {
    __shared__ float Wms[HIDC * HIDC];
    __shared__ float Wss[HIDC * HIDC];
    __shared__ float tile[64 * HIDC];   // 16 KB
    __shared__ float spool[128];        // 64 mu + 64 sig

    for (int i = threadIdx.x; i < HIDC * HIDC / 4; i += 256) {
        reinterpret_cast<float4*>(Wms)[i] = reinterpret_cast<const float4*>(Wmu)[i];
        reinterpret_cast<float4*>(Wss)[i] = reinterpret_cast<const float4*>(Wsig)[i];
    }
    if (threadIdx.x < 128) spool[threadIdx.x] = 0.f;

    const int row0 = blockIdx.x * 64;

    // ---- Phase A: gather 64 nodes into smem tile (8 lanes/node, 2 nodes/thread) ----
    {
        int c  = threadIdx.x & 7;      // 8-half slice
        int ng = threadIdx.x >> 3;     // 0..31
#pragma unroll
        for (int pp = 0; pp < 2; pp++) {
            int ln = ng + 32 * pp;     // local node 0..63
            int node = row0 + ln;
            float acc[8];
            if (node < N) {
                float di = g_dinv[node];
                float self = di * di;
                uint4 v = *reinterpret_cast<const uint4*>(&g_h1[(long long)node * HIDC + c * 8]);
                const __half2* h = reinterpret_cast<const __half2*>(&v);
#pragma unroll
                for (int j = 0; j < 4; j++) {
                    float2 f = __half22float2(h[j]);
                    acc[2 * j]     = f.x * self;
                    acc[2 * j + 1] = f.y * self;
                }
                csr_gather_h(g_h1, node, c, acc);
            } else {
#pragma unroll
                for (int j = 0; j < 8; j++) acc[j] = 0.f;
            }
            reinterpret_cast<float4*>(&tile[ln * HIDC + c * 8])[0] =
                make_float4(acc[0], acc[1], acc[2], acc[3]);
            reinterpret_cast<float4*>(&tile[ln * HIDC + c * 8 + 4])[0] =
                make_float4(acc[4], acc[5], acc[6], acc[7]);
        }
    }
    __syncthreads();

    // ---- Phase B: dual GEMM from smem + bias + ELU + pool ----
    const int q  = threadIdx.x & 15;
    const int rg = threadIdx.x >> 4;   // 0..15

    float4 am[4], as4[4];
    int rows[4]; bool valid[4];
#pragma unroll
    for (int rr = 0; rr < 4; rr++) {
        rows[rr] = row0 + rg + 16 * rr;
        valid[rr] = rows[rr] < N;
        am[rr]  = make_float4(0.f, 0.f, 0.f, 0.f);
        as4[rr] = make_float4(0.f, 0.f, 0.f, 0.f);
    }

    for (int k4 = 0; k4 < HIDC / 4; k4++) {
        float4 a[4];
#pragma unroll
        for (int rr = 0; rr < 4; rr++)
            a[rr] = reinterpret_cast<const float4*>(&tile[(rg + 16 * rr) * HIDC + k4 * 4])[0];
#pragma unroll
        for (int kk = 0; kk < 4; kk++) {
            float4 wm = reinterpret_cast<const float4*>(&Wms[(k4 * 4 + kk) * HIDC + q * 4])[0];
            float4 ws = reinterpret_cast<const float4*>(&Wss[(k4 * 4 + kk) * HIDC + q * 4])[0];
#pragma unroll
            for (int rr = 0; rr < 4; rr++) {
                float av = (&a[rr].x)[kk];
                am[rr]  = fma4(wm, av, am[rr]);
                as4[rr] = fma4(ws, av, as4[rr]);
            }
        }
    }

    float4 bbm = reinterpret_cast<const float4*>(&bmu[q * 4])[0];
    float4 bbs = reinterpret_cast<const float4*>(&bsig[q * 4])[0];
#pragma unroll
    for (int rr = 0; rr < 4; rr++) {
        am[rr]  = elu4(add4(am[rr], bbm));
        as4[rr] = elu4(add4(as4[rr], bbs));
    }

    int lastRow = min(row0 + 63, N - 1);
    int g0 = batch[row0];
    int g1 = batch[lastRow];

    if (g0 == g1) {
        float4 sm = make_float4(0.f, 0.f, 0.f, 0.f);
        float4 ss = make_float4(0.f, 0.f, 0.f, 0.f);
#pragma unroll
        for (int rr = 0; rr < 4; rr++) {
            if (valid[rr]) { sm = add4(sm, am[rr]); ss = add4(ss, as4[rr]); }
        }
        atomicAdd(&spool[q * 4 + 0], sm.x);
        atomicAdd(&spool[q * 4 + 1], sm.y);
        atomicAdd(&spool[q * 4 + 2], sm.z);
        atomicAdd(&spool[q * 4 + 3], sm.w);
        atomicAdd(&spool[64 + q * 4 + 0], ss.x);
        atomicAdd(&spool[64 + q * 4 + 1], ss.y);
        atomicAdd(&spool[64 + q * 4 + 2], ss.z);
        atomicAdd(&spool[64 + q * 4 + 3], ss.w);
        __syncthreads();
        if (threadIdx.x < 32) {
            int half = threadIdx.x >> 4;
            int cc   = threadIdx.x & 15;
            float4 v = reinterpret_cast<const float4*>(&spool[half * 64 + cc * 4])[0];
            red_add_f32x4(&g_sums[(long long)(half * 64 + g0) * HIDC + cc * 4], v);
        }
        if (threadIdx.x == 0) {
            int cnt = min(N - row0, 64);
            red_add_f32(&g_cntf[g0], (float)cnt);
        }
    } else {
#pragma unroll
        for (int rr = 0; rr < 4; rr++) {
            if (!valid[rr]) continue;
            int g = batch[rows[rr]];
            red_add_f32x4(&g_sums[(long long)(0 * 64 + g) * HIDC + q * 4], am[rr]);
            red_add_f32x4(&g_sums[(long long)(1 * 64 + g) * HIDC + q * 4], as4[rr]);
            if (q == 0) red_add_f32(&g_cntf[g], 1.0f);
        }
    }
}

// Final: divide by counts, write [z_mu ; z_sigma] to d_out.
__global__ void k_final(float* __restrict__ out, int G) {
    int tid = blockIdx.x * blockDim.x + threadIdx.x;
    int total = 2 * G * HIDC;
    if (tid >= total) return;
    int t = tid / (G * HIDC);
    int rem = tid - t * G * HIDC;
    int g = rem >> 6;
    int c = rem & 63;
    float cnt = fmaxf(g_cntf[g], 1.0f);
    out[tid] = g_sums[(long long)(t * 64 + g) * HIDC + c] / cnt;
}

// ---------------- launch ----------------
extern "C" void kernel_launch(void* const* d_in, const int* in_sizes, int n_in,
                              void* d_out, int out_size) {
    const float* x     = (const float*)d_in[0];
    const int*   ei    = (const int*)d_in[1];
    const int*   batch = (const int*)d_in[2];

    int N = in_sizes[0] / INDIM;   // 50000
    int E = in_sizes[1] / 2;       // 800000
    int G = out_size / (2 * HIDC); // 64

    int wi = 3;
    if (in_sizes[3] == 1) wi = 4;  // num_graphs may be materialized
    const float* W1   = (const float*)d_in[wi + 0];
    const float* b1   = (const float*)d_in[wi + 1];
    const float* Wmu  = (const float*)d_in[wi + 2];
    const float* bmu  = (const float*)d_in[wi + 3];
    const float* Wsig = (const float*)d_in[wi + 4];
    const float* bsig = (const float*)d_in[wi + 5];
    float* out = (float*)d_out;

    const int* src = ei;
    const int* dst = ei + E;

    // Fork-join: CSR build chain on the main (capture) stream, gemm1 on a
    // side stream — they share no data until k_gather1.
    cudaStream_t s2;
    cudaStreamCreateWithFlags(&s2, cudaStreamNonBlocking);
    cudaEvent_t evF, evJ;
    cudaEventCreateWithFlags(&evF, cudaEventDisableTiming);
    cudaEventCreateWithFlags(&evJ, cudaEventDisableTiming);

    cudaEventRecord(evF, 0);
    cudaStreamWaitEvent(s2, evF, 0);
    k_gemm1<<<(N + 127) / 128, 256, 0, s2>>>(x, W1, N);   // branch B
    cudaEventRecord(evJ, s2);

    // branch A: CSR build
    k_zero<<<(NN + 255) / 256, 256>>>();
    k_deg<<<(E + 255) / 256, 256>>>(dst, E);
    k_scan1<<<SCAN_NB, SCAN_BLK>>>(N);
    k_scan3<<<(N + 255) / 256, 256>>>(N, E);
    k_fill<<<(E + 255) / 256, 256>>>(src, dst, E);

    cudaStreamWaitEvent(0, evJ, 0);   // join before gather1

    {
        long long t = (long long)N * 8;
        k_gather1<<<(unsigned)((t + 255) / 256), 256>>>(b1, N);
    }
    k_gather2gemm2pool<<<(N + 63) / 64, 256>>>(Wmu, bmu, Wsig, bsig, batch, N);
    k_final<<<(2 * G * HIDC + 255) / 256, 256>>>(out, G);

    cudaEventDestroy(evF);
    cudaEventDestroy(evJ);
    cudaStreamDestroy(s2);
}